// round 7
// baseline (speedup 1.0000x reference)
#include <cuda_runtime.h>
#include <cuda_bf16.h>
#include <cstdint>

#define B_ 32
#define L_ 1024
#define D_ 1024
typedef __nv_bfloat16 bf16;

// ---------------------------------------------------------------------------
// Scratch (device globals; no allocation in kernel_launch)
// ---------------------------------------------------------------------------
__device__ bf16  g_xh [(size_t)B_ * L_ * D_];   // x hi split, [b, l, d]
__device__ bf16  g_xl [(size_t)B_ * L_ * D_];   // x lo split
__device__ bf16  g_xth[(size_t)B_ * L_ * D_];   // x^T hi, [b, d, l]
__device__ bf16  g_xtl[(size_t)B_ * L_ * D_];   // x^T lo
__device__ float g_scores[(size_t)B_ * L_ * L_];
__device__ bf16  g_ah [(size_t)B_ * L_ * L_];   // alpha hi
__device__ bf16  g_al [(size_t)B_ * L_ * L_];   // alpha lo

// ---------------------------------------------------------------------------
// PTX helpers (baseline ISA only — harness targets plain sm_103, no tcgen05)
// ---------------------------------------------------------------------------
__device__ __forceinline__ uint32_t smem_u32(const void* p) {
    uint32_t a;
    asm("{ .reg .u64 t; cvta.to.shared.u64 t, %1; cvt.u32.u64 %0, t; }" : "=r"(a) : "l"(p));
    return a;
}
#define CP_COMMIT() asm volatile("cp.async.commit_group;" ::: "memory")
#define CP_WAIT2()  asm volatile("cp.async.wait_group 2;" ::: "memory")
#define CP_WAIT0()  asm volatile("cp.async.wait_group 0;" ::: "memory")

__device__ __forceinline__ void cp16(uint32_t dst, const void* src) {
    asm volatile("cp.async.cg.shared.global [%0], [%1], 16;" :: "r"(dst), "l"(src));
}
__device__ __forceinline__ void ldsm4(uint32_t* r, uint32_t addr) {
    asm volatile("ldmatrix.sync.aligned.m8n8.x4.shared.b16 {%0,%1,%2,%3}, [%4];"
                 : "=r"(r[0]), "=r"(r[1]), "=r"(r[2]), "=r"(r[3]) : "r"(addr));
}
__device__ __forceinline__ void mma16816(float* c, const uint32_t* a, const uint32_t* b) {
    asm volatile(
        "mma.sync.aligned.m16n8k16.row.col.f32.bf16.bf16.f32 "
        "{%0,%1,%2,%3}, {%4,%5,%6,%7}, {%8,%9}, {%0,%1,%2,%3};"
        : "+f"(c[0]), "+f"(c[1]), "+f"(c[2]), "+f"(c[3])
        : "r"(a[0]), "r"(a[1]), "r"(a[2]), "r"(a[3]), "r"(b[0]), "r"(b[1]));
}

// ---------------------------------------------------------------------------
// Kernel 0: split x into bf16 hi/lo, plus transposed copies.
// ---------------------------------------------------------------------------
__global__ __launch_bounds__(256) void conv_kernel(const float* __restrict__ x)
{
    __shared__ bf16 sh[32][33];
    __shared__ bf16 sl[32][33];
    const int b = blockIdx.z;
    const int d0 = blockIdx.x * 32, l0 = blockIdx.y * 32;
    const int tx = threadIdx.x, ty = threadIdx.y;
    const float* X = x + (size_t)b * L_ * D_;
    const size_t bo = (size_t)b * L_ * D_;

#pragma unroll
    for (int i = 0; i < 4; i++) {
        int row = ty + i * 8;
        float v = X[(size_t)(l0 + row) * D_ + d0 + tx];
        bf16 h = __float2bfloat16(v);
        bf16 l = __float2bfloat16(v - __bfloat162float(h));
        size_t o = bo + (size_t)(l0 + row) * D_ + d0 + tx;
        g_xh[o] = h; g_xl[o] = l;
        sh[row][tx] = h; sl[row][tx] = l;
    }
    __syncthreads();
#pragma unroll
    for (int i = 0; i < 4; i++) {
        int row = ty + i * 8;
        size_t o = bo + (size_t)(d0 + row) * L_ + l0 + tx;
        g_xth[o] = sh[tx][row];
        g_xtl[o] = sl[tx][row];
    }
}

// ---------------------------------------------------------------------------
// Split-bf16 HMMA GEMM: 128x128 CTA tile, 8 warps (64x32 warptile),
// mma.sync m16n8k16, KC=16 chunks in a 4-stage cp.async ring.
// 48B smem rows (16B-aligned cp16, same conflict class as 80B rows).
// __launch_bounds__(256, 2): 2 CTAs/SM.
// ---------------------------------------------------------------------------
#define KC 16
#define NSTAGE 4
#define NCHUNK (1024 / KC)              // 64
#define TROW 24                         // elements per smem row (48 bytes)
#define TILE_BYTES (128 * TROW * 2)     // 6144
#define STAGE_BYTES (4 * TILE_BYTES)    // 24576: Ah, Al, Bh, Bl
#define SMEM_GEMM (NSTAGE * STAGE_BYTES) // 98304; x2 CTAs = 192KB <= 228KB

__device__ __forceinline__ void fill_stage(uint32_t st,
                                           const bf16* __restrict__ Ah,
                                           const bf16* __restrict__ Al,
                                           const bf16* __restrict__ Bh,
                                           const bf16* __restrict__ Bl,
                                           int rowBase, int colBase, int k0, int tid)
{
    const int row = tid >> 1, seg = tid & 1;      // 128 rows x 2 16B-segs
    const uint32_t d = st + row * 48 + seg * 16;
    const size_t so = (size_t)row * 1024 + k0 + seg * 8;
    cp16(d + 0 * TILE_BYTES, Ah + (size_t)rowBase * 1024 + so);
    cp16(d + 1 * TILE_BYTES, Al + (size_t)rowBase * 1024 + so);
    cp16(d + 2 * TILE_BYTES, Bh + (size_t)colBase * 1024 + so);
    cp16(d + 3 * TILE_BYTES, Bl + (size_t)colBase * 1024 + so);
}

template <bool SCORES>
__global__ __launch_bounds__(256, 2) void gemm_kernel(const int* __restrict__ xmask,
                                                      float* __restrict__ gout)
{
    extern __shared__ char smem[];
    const uint32_t sb = smem_u32(smem);
    const int tid = threadIdx.x;
    const int wid = tid >> 5, lane = tid & 31;
    const int wr = wid >> 2, wc = wid & 3;          // 2x4 warp grid
    const int b = blockIdx.z;
    const int rowBase = blockIdx.y * 128;
    const int colBase = blockIdx.x * 128;

    const bf16 *Ah, *Al, *Bh, *Bl;
    float* O;
    const size_t bo = (size_t)b * 1024 * 1024;
    if (SCORES) {
        Ah = g_xh + bo; Al = g_xl + bo; Bh = g_xh + bo; Bl = g_xl + bo;
        O = g_scores + bo;
    } else {
        Ah = g_ah + bo; Al = g_al + bo; Bh = g_xth + bo; Bl = g_xtl + bo;
        O = gout + bo;
    }

    float acc[4][4][4];
#pragma unroll
    for (int i = 0; i < 4; i++)
#pragma unroll
        for (int j = 0; j < 4; j++)
#pragma unroll
            for (int k = 0; k < 4; k++) acc[i][j][k] = 0.f;

    // ldmatrix per-lane address components (KC=16: single k16 step per chunk)
    const uint32_t aOff = (uint32_t)(wr * 64 + (lane & 15)) * 48 + (uint32_t)(lane >> 4) * 16;
    const uint32_t bRowBase = (uint32_t)(wc * 32 + ((lane >> 4) << 3) + (lane & 7)); // + n2*16
    const uint32_t bOff0 = bRowBase * 48 + (uint32_t)((lane >> 3) & 1) * 16;

    // prologue: fill stages 0..2
#pragma unroll
    for (int s = 0; s < NSTAGE - 1; s++) {
        fill_stage(sb + s * STAGE_BYTES, Ah, Al, Bh, Bl, rowBase, colBase, s * KC, tid);
        CP_COMMIT();
    }

    for (int c = 0; c < NCHUNK; c++) {
        if (c >= NCHUNK - 2) CP_WAIT0(); else CP_WAIT2();
        __syncthreads();
        const uint32_t st = sb + (c & 3) * STAGE_BYTES;

        // B fragments (16 regs)
        uint32_t bh[2][4], bl[2][4];
#pragma unroll
        for (int n2 = 0; n2 < 2; n2++) {
            uint32_t off = bOff0 + (uint32_t)n2 * (16 * 48);
            ldsm4(bh[n2], st + 2 * TILE_BYTES + off);
            ldsm4(bl[n2], st + 3 * TILE_BYTES + off);
        }
        // Stream A fragments
#pragma unroll
        for (int mf = 0; mf < 4; mf++) {
            uint32_t ah[4], al[4];
            uint32_t off = aOff + (uint32_t)mf * (16 * 48);
            ldsm4(ah, st + 0 * TILE_BYTES + off);
            ldsm4(al, st + 1 * TILE_BYTES + off);
#pragma unroll
            for (int nf = 0; nf < 4; nf++) {
                const uint32_t* bhp = &bh[nf >> 1][(nf & 1) * 2];
                const uint32_t* blp = &bl[nf >> 1][(nf & 1) * 2];
                mma16816(acc[mf][nf], ah, bhp);
                mma16816(acc[mf][nf], al, bhp);
                mma16816(acc[mf][nf], ah, blp);
            }
        }
        __syncthreads();
        if (c + NSTAGE - 1 < NCHUNK) {
            fill_stage(sb + ((c + NSTAGE - 1) & 3) * STAGE_BYTES,
                       Ah, Al, Bh, Bl, rowBase, colBase, (c + NSTAGE - 1) * KC, tid);
            CP_COMMIT();
        }
    }

    // epilogue
    const int rb = rowBase + wr * 64 + (lane >> 2);
    const int cb = colBase + wc * 32 + (lane & 3) * 2;
    const int* mrow = SCORES ? (xmask + b * L_) : nullptr;

#pragma unroll
    for (int mf = 0; mf < 4; mf++) {
        const int r = rb + mf * 16;
#pragma unroll
        for (int nf = 0; nf < 4; nf++) {
            const int cc = cb + nf * 8;
            float v0 = acc[mf][nf][0], v1 = acc[mf][nf][1];   // row r,   cols cc, cc+1
            float v2 = acc[mf][nf][2], v3 = acc[mf][nf][3];   // row r+8, cols cc, cc+1
            if (SCORES) {
                const int m0 = mrow[cc], m1 = mrow[cc + 1];
                if (r == cc || m0 == 0) v0 = 0.f;
                if (r == cc + 1 || m1 == 0) v1 = 0.f;
                if (r + 8 == cc || m0 == 0) v2 = 0.f;
                if (r + 8 == cc + 1 || m1 == 0) v3 = 0.f;
            }
            *(float2*)(O + (size_t)r * 1024 + cc) = make_float2(v0, v1);
            *(float2*)(O + (size_t)(r + 8) * 1024 + cc) = make_float2(v2, v3);
        }
    }
}

// ---------------------------------------------------------------------------
// Softmax-renormalize: reads g_scores, writes alpha as bf16 hi/lo splits.
// ---------------------------------------------------------------------------
__global__ __launch_bounds__(256) void softmax_kernel(const int* __restrict__ xmask)
{
    const int row = blockIdx.x;
    const int b = row >> 10;
    const float* srow = g_scores + (size_t)row * L_;
    const int* mrow = xmask + b * L_;
    const int tid = threadIdx.x;

    float4 v = *(const float4*)(srow + tid * 4);
    int4 mk = *(const int4*)(mrow + tid * 4);

    __shared__ float red[8];
    float mx = fmaxf(fmaxf(v.x, v.y), fmaxf(v.z, v.w));
#pragma unroll
    for (int o = 16; o > 0; o >>= 1) mx = fmaxf(mx, __shfl_xor_sync(0xffffffffu, mx, o));
    if ((tid & 31) == 0) red[tid >> 5] = mx;
    __syncthreads();
    if (tid < 32) {
        float t = (tid < 8) ? red[tid] : -3.4e38f;
#pragma unroll
        for (int o = 4; o > 0; o >>= 1) t = fmaxf(t, __shfl_xor_sync(0xffffffffu, t, o));
        if (tid == 0) red[0] = t;
    }
    __syncthreads();
    mx = red[0];
    __syncthreads();

    float e0 = __expf(v.x - mx), e1 = __expf(v.y - mx);
    float e2 = __expf(v.z - mx), e3 = __expf(v.w - mx);
    float m0 = (mk.x != 0) ? 1.f : 0.f, m1 = (mk.y != 0) ? 1.f : 0.f;
    float m2 = (mk.z != 0) ? 1.f : 0.f, m3 = (mk.w != 0) ? 1.f : 0.f;
    float zf = e0 + e1 + e2 + e3;
    float sm = e0 * m0 + e1 * m1 + e2 * m2 + e3 * m3;

    float2 s2 = make_float2(zf, sm);
#pragma unroll
    for (int o = 16; o > 0; o >>= 1) {
        s2.x += __shfl_xor_sync(0xffffffffu, s2.x, o);
        s2.y += __shfl_xor_sync(0xffffffffu, s2.y, o);
    }
    __shared__ float redz[8], redm[8];
    if ((tid & 31) == 0) { redz[tid >> 5] = s2.x; redm[tid >> 5] = s2.y; }
    __syncthreads();
    if (tid < 32) {
        float tz = (tid < 8) ? redz[tid] : 0.f;
        float tm = (tid < 8) ? redm[tid] : 0.f;
#pragma unroll
        for (int o = 4; o > 0; o >>= 1) {
            tz += __shfl_xor_sync(0xffffffffu, tz, o);
            tm += __shfl_xor_sync(0xffffffffu, tm, o);
        }
        if (tid == 0) { redz[0] = tz; redm[0] = tm; }
    }
    __syncthreads();
    const float inv = 1.f / (redm[0] + 1e-13f * redz[0]);

    float a[4];
    a[0] = e0 * m0 * inv; a[1] = e1 * m1 * inv;
    a[2] = e2 * m2 * inv; a[3] = e3 * m3 * inv;

    const size_t o = (size_t)row * L_ + tid * 4;
    bf16 hh[4], ll[4];
#pragma unroll
    for (int i = 0; i < 4; i++) {
        hh[i] = __float2bfloat16(a[i]);
        ll[i] = __float2bfloat16(a[i] - __bfloat162float(hh[i]));
    }
    *(uint2*)(g_ah + o) = *(uint2*)hh;
    *(uint2*)(g_al + o) = *(uint2*)ll;
}

// ---------------------------------------------------------------------------
extern "C" void kernel_launch(void* const* d_in, const int* in_sizes, int n_in,
                              void* d_out, int out_size)
{
    const float* x = (const float*)d_in[0];
    const int* xmask = (const int*)d_in[1];
    float* out = (float*)d_out;

    cudaFuncSetAttribute(gemm_kernel<true>,
                         cudaFuncAttributeMaxDynamicSharedMemorySize, SMEM_GEMM);
    cudaFuncSetAttribute(gemm_kernel<false>,
                         cudaFuncAttributeMaxDynamicSharedMemorySize, SMEM_GEMM);

    conv_kernel<<<dim3(32, 32, B_), dim3(32, 8)>>>(x);

    gemm_kernel<true><<<dim3(8, 8, B_), 256, SMEM_GEMM>>>(xmask, nullptr);

    softmax_kernel<<<B_ * L_, 256>>>(xmask);

    gemm_kernel<false><<<dim3(8, 8, B_), 256, SMEM_GEMM>>>(xmask, out);
}

// round 8
// speedup vs baseline: 1.1831x; 1.1831x over previous
#include <cuda_runtime.h>
#include <cuda_bf16.h>
#include <cstdint>

#define B_ 32
#define L_ 1024
#define D_ 1024
typedef __nv_bfloat16 bf16;

// ---------------------------------------------------------------------------
// Scratch (device globals; no allocation in kernel_launch)
// ---------------------------------------------------------------------------
__device__ bf16  g_xh [(size_t)B_ * L_ * D_];   // x hi split, [b, l, d]
__device__ bf16  g_xl [(size_t)B_ * L_ * D_];   // x lo split
__device__ bf16  g_xth[(size_t)B_ * L_ * D_];   // x^T hi, [b, d, l]
__device__ bf16  g_xtl[(size_t)B_ * L_ * D_];   // x^T lo
__device__ float g_scores[(size_t)B_ * L_ * L_];
__device__ bf16  g_ah [(size_t)B_ * L_ * L_];   // alpha hi
__device__ bf16  g_al [(size_t)B_ * L_ * L_];   // alpha lo

// ---------------------------------------------------------------------------
// PTX helpers (baseline ISA only — harness targets plain sm_103, no tcgen05)
// ---------------------------------------------------------------------------
__device__ __forceinline__ uint32_t smem_u32(const void* p) {
    uint32_t a;
    asm("{ .reg .u64 t; cvta.to.shared.u64 t, %1; cvt.u32.u64 %0, t; }" : "=r"(a) : "l"(p));
    return a;
}
#define CP_COMMIT() asm volatile("cp.async.commit_group;" ::: "memory")
#define CP_WAIT1()  asm volatile("cp.async.wait_group 1;" ::: "memory")
#define CP_WAIT0()  asm volatile("cp.async.wait_group 0;" ::: "memory")

__device__ __forceinline__ void cp16(uint32_t dst, const void* src) {
    asm volatile("cp.async.cg.shared.global [%0], [%1], 16;" :: "r"(dst), "l"(src));
}
__device__ __forceinline__ void ldsm4(uint32_t* r, uint32_t addr) {
    asm volatile("ldmatrix.sync.aligned.m8n8.x4.shared.b16 {%0,%1,%2,%3}, [%4];"
                 : "=r"(r[0]), "=r"(r[1]), "=r"(r[2]), "=r"(r[3]) : "r"(addr));
}
__device__ __forceinline__ void mma16816(float* c, const uint32_t* a, const uint32_t* b) {
    asm volatile(
        "mma.sync.aligned.m16n8k16.row.col.f32.bf16.bf16.f32 "
        "{%0,%1,%2,%3}, {%4,%5,%6,%7}, {%8,%9}, {%0,%1,%2,%3};"
        : "+f"(c[0]), "+f"(c[1]), "+f"(c[2]), "+f"(c[3])
        : "r"(a[0]), "r"(a[1]), "r"(a[2]), "r"(a[3]), "r"(b[0]), "r"(b[1]));
}

// ---------------------------------------------------------------------------
// Kernel 0: split x into bf16 hi/lo, plus transposed copies.
// ---------------------------------------------------------------------------
__global__ __launch_bounds__(256) void conv_kernel(const float* __restrict__ x)
{
    __shared__ bf16 sh[32][33];
    __shared__ bf16 sl[32][33];
    const int b = blockIdx.z;
    const int d0 = blockIdx.x * 32, l0 = blockIdx.y * 32;
    const int tx = threadIdx.x, ty = threadIdx.y;
    const float* X = x + (size_t)b * L_ * D_;
    const size_t bo = (size_t)b * L_ * D_;

#pragma unroll
    for (int i = 0; i < 4; i++) {
        int row = ty + i * 8;
        float v = X[(size_t)(l0 + row) * D_ + d0 + tx];
        bf16 h = __float2bfloat16(v);
        bf16 l = __float2bfloat16(v - __bfloat162float(h));
        size_t o = bo + (size_t)(l0 + row) * D_ + d0 + tx;
        g_xh[o] = h; g_xl[o] = l;
        sh[row][tx] = h; sl[row][tx] = l;
    }
    __syncthreads();
#pragma unroll
    for (int i = 0; i < 4; i++) {
        int row = ty + i * 8;
        size_t o = bo + (size_t)(d0 + row) * L_ + l0 + tx;
        g_xth[o] = sh[tx][row];
        g_xtl[o] = sl[tx][row];
    }
}

// ---------------------------------------------------------------------------
// Split-bf16 HMMA GEMM: 256x128 CTA tile, 512 threads (16 warps, 64x32
// warptiles in a 4x4 grid), mma.sync m16n8k16, KC=32 chunks in a 3-stage
// cp.async ring with ONE __syncthreads per chunk (fill after the sync targets
// the buffer whose reads finished in iteration c-1, ordered by that sync).
// 80B smem rows: conflict-free ldmatrix (80*8 = 5*128 cycles all 8 slots).
// ---------------------------------------------------------------------------
#define KC 32
#define NSTAGE 3
#define NCHUNK (1024 / KC)              // 32
#define TROW 40                         // elements per smem row (80 bytes)
#define ATILE_B (256 * TROW * 2)        // 20480
#define BTILE_B (128 * TROW * 2)        // 10240
#define AH_OFF 0
#define AL_OFF ATILE_B
#define BH_OFF (2 * ATILE_B)
#define BL_OFF (2 * ATILE_B + BTILE_B)
#define STAGE_BYTES (2 * ATILE_B + 2 * BTILE_B)   // 61440
#define SMEM_GEMM (NSTAGE * STAGE_BYTES)          // 184320 (180KB)

__device__ __forceinline__ void fill_stage(uint32_t st,
                                           const bf16* __restrict__ Ah,
                                           const bf16* __restrict__ Al,
                                           const bf16* __restrict__ Bh,
                                           const bf16* __restrict__ Bl,
                                           int rowBase, int colBase, int k0, int tid)
{
    // A tiles: 256 rows x 4 16B-segs = 1024 cp16s each; 512 threads -> 2 each
#pragma unroll
    for (int i = 0; i < 2; i++) {
        int idx = i * 512 + tid;
        int row = idx >> 2, seg = idx & 3;
        uint32_t d = st + row * 80 + seg * 16;
        size_t so = (size_t)(rowBase + row) * 1024 + k0 + seg * 8;
        cp16(d + AH_OFF, Ah + so);
        cp16(d + AL_OFF, Al + so);
    }
    // B tiles: 128 rows x 4 segs = 512 cp16s each; one per thread
    {
        int row = tid >> 2, seg = tid & 3;
        uint32_t d = st + row * 80 + seg * 16;
        size_t so = (size_t)(colBase + row) * 1024 + k0 + seg * 8;
        cp16(d + BH_OFF, Bh + so);
        cp16(d + BL_OFF, Bl + so);
    }
}

template <bool SCORES>
__global__ __launch_bounds__(512, 1) void gemm_kernel(const int* __restrict__ xmask,
                                                      float* __restrict__ gout)
{
    extern __shared__ char smem[];
    const uint32_t sb = smem_u32(smem);
    const int tid = threadIdx.x;
    const int wid = tid >> 5, lane = tid & 31;
    const int wr = wid >> 2, wc = wid & 3;          // 4x4 warp grid
    const int b = blockIdx.z;
    const int rowBase = blockIdx.y * 256;
    const int colBase = blockIdx.x * 128;

    const bf16 *Ah, *Al, *Bh, *Bl;
    float* O;
    const size_t bo = (size_t)b * 1024 * 1024;
    if (SCORES) {
        Ah = g_xh + bo; Al = g_xl + bo; Bh = g_xh + bo; Bl = g_xl + bo;
        O = g_scores + bo;
    } else {
        Ah = g_ah + bo; Al = g_al + bo; Bh = g_xth + bo; Bl = g_xtl + bo;
        O = gout + bo;
    }

    float acc[4][4][4];
#pragma unroll
    for (int i = 0; i < 4; i++)
#pragma unroll
        for (int j = 0; j < 4; j++)
#pragma unroll
            for (int k = 0; k < 4; k++) acc[i][j][k] = 0.f;

    // ldmatrix per-lane address components
    const uint32_t aRowOff = (uint32_t)(wr * 64 + (lane & 15)) * 80;   // + mf*16*80
    const uint32_t aColSel = (uint32_t)(lane >> 4) * 8;                // element offset
    const uint32_t bRowBase = (uint32_t)(wc * 32 + ((lane >> 4) << 3) + (lane & 7)); // + n2*16
    const uint32_t bColSel = (uint32_t)((lane >> 3) & 1) * 8;

    // prologue: fill stages 0,1
#pragma unroll
    for (int s = 0; s < NSTAGE - 1; s++) {
        fill_stage(sb + s * STAGE_BYTES, Ah, Al, Bh, Bl, rowBase, colBase, s * KC, tid);
        CP_COMMIT();
    }

    int s_cur = 0, s_nxt = 2;             // c%3, (c+2)%3
    for (int c = 0; c < NCHUNK; c++) {
        if (c >= NCHUNK - 1) CP_WAIT0(); else CP_WAIT1();
        __syncthreads();
        const uint32_t st = sb + s_cur * STAGE_BYTES;

        // fill the furthest-ahead stage (its reads ended in iter c-1, ordered
        // by the sync above) — ONE barrier per chunk.
        if (c + NSTAGE - 1 < NCHUNK) {
            fill_stage(sb + s_nxt * STAGE_BYTES, Ah, Al, Bh, Bl,
                       rowBase, colBase, (c + NSTAGE - 1) * KC, tid);
            CP_COMMIT();
        }

#pragma unroll
        for (int kk = 0; kk < KC; kk += 16) {
            // B fragments (16 regs)
            uint32_t bh[2][4], bl[2][4];
#pragma unroll
            for (int n2 = 0; n2 < 2; n2++) {
                uint32_t off = (bRowBase + (uint32_t)n2 * 16) * 80 + (kk + bColSel) * 2;
                ldsm4(bh[n2], st + BH_OFF + off);
                ldsm4(bl[n2], st + BL_OFF + off);
            }
            // Stream A fragments
#pragma unroll
            for (int mf = 0; mf < 4; mf++) {
                uint32_t ah[4], al[4];
                uint32_t off = aRowOff + (uint32_t)mf * (16 * 80) + (kk + aColSel) * 2;
                ldsm4(ah, st + AH_OFF + off);
                ldsm4(al, st + AL_OFF + off);
#pragma unroll
                for (int nf = 0; nf < 4; nf++) {
                    const uint32_t* bhp = &bh[nf >> 1][(nf & 1) * 2];
                    const uint32_t* blp = &bl[nf >> 1][(nf & 1) * 2];
                    mma16816(acc[mf][nf], ah, bhp);
                    mma16816(acc[mf][nf], al, bhp);
                    mma16816(acc[mf][nf], ah, blp);
                }
            }
        }
        s_cur++; if (s_cur == NSTAGE) s_cur = 0;
        s_nxt++; if (s_nxt == NSTAGE) s_nxt = 0;
    }

    // epilogue
    const int rb = rowBase + wr * 64 + (lane >> 2);
    const int cb = colBase + wc * 32 + (lane & 3) * 2;
    const int* mrow = SCORES ? (xmask + b * L_) : nullptr;

#pragma unroll
    for (int mf = 0; mf < 4; mf++) {
        const int r = rb + mf * 16;
#pragma unroll
        for (int nf = 0; nf < 4; nf++) {
            const int cc = cb + nf * 8;
            float v0 = acc[mf][nf][0], v1 = acc[mf][nf][1];   // row r,   cols cc, cc+1
            float v2 = acc[mf][nf][2], v3 = acc[mf][nf][3];   // row r+8, cols cc, cc+1
            if (SCORES) {
                const int m0 = mrow[cc], m1 = mrow[cc + 1];
                if (r == cc || m0 == 0) v0 = 0.f;
                if (r == cc + 1 || m1 == 0) v1 = 0.f;
                if (r + 8 == cc || m0 == 0) v2 = 0.f;
                if (r + 8 == cc + 1 || m1 == 0) v3 = 0.f;
            }
            *(float2*)(O + (size_t)r * 1024 + cc) = make_float2(v0, v1);
            *(float2*)(O + (size_t)(r + 8) * 1024 + cc) = make_float2(v2, v3);
        }
    }
}

// ---------------------------------------------------------------------------
// Softmax-renormalize: reads g_scores, writes alpha as bf16 hi/lo splits.
// ---------------------------------------------------------------------------
__global__ __launch_bounds__(256) void softmax_kernel(const int* __restrict__ xmask)
{
    const int row = blockIdx.x;
    const int b = row >> 10;
    const float* srow = g_scores + (size_t)row * L_;
    const int* mrow = xmask + b * L_;
    const int tid = threadIdx.x;

    float4 v = *(const float4*)(srow + tid * 4);
    int4 mk = *(const int4*)(mrow + tid * 4);

    __shared__ float red[8];
    float mx = fmaxf(fmaxf(v.x, v.y), fmaxf(v.z, v.w));
#pragma unroll
    for (int o = 16; o > 0; o >>= 1) mx = fmaxf(mx, __shfl_xor_sync(0xffffffffu, mx, o));
    if ((tid & 31) == 0) red[tid >> 5] = mx;
    __syncthreads();
    if (tid < 32) {
        float t = (tid < 8) ? red[tid] : -3.4e38f;
#pragma unroll
        for (int o = 4; o > 0; o >>= 1) t = fmaxf(t, __shfl_xor_sync(0xffffffffu, t, o));
        if (tid == 0) red[0] = t;
    }
    __syncthreads();
    mx = red[0];
    __syncthreads();

    float e0 = __expf(v.x - mx), e1 = __expf(v.y - mx);
    float e2 = __expf(v.z - mx), e3 = __expf(v.w - mx);
    float m0 = (mk.x != 0) ? 1.f : 0.f, m1 = (mk.y != 0) ? 1.f : 0.f;
    float m2 = (mk.z != 0) ? 1.f : 0.f, m3 = (mk.w != 0) ? 1.f : 0.f;
    float zf = e0 + e1 + e2 + e3;
    float sm = e0 * m0 + e1 * m1 + e2 * m2 + e3 * m3;

    float2 s2 = make_float2(zf, sm);
#pragma unroll
    for (int o = 16; o > 0; o >>= 1) {
        s2.x += __shfl_xor_sync(0xffffffffu, s2.x, o);
        s2.y += __shfl_xor_sync(0xffffffffu, s2.y, o);
    }
    __shared__ float redz[8], redm[8];
    if ((tid & 31) == 0) { redz[tid >> 5] = s2.x; redm[tid >> 5] = s2.y; }
    __syncthreads();
    if (tid < 32) {
        float tz = (tid < 8) ? redz[tid] : 0.f;
        float tm = (tid < 8) ? redm[tid] : 0.f;
#pragma unroll
        for (int o = 4; o > 0; o >>= 1) {
            tz += __shfl_xor_sync(0xffffffffu, tz, o);
            tm += __shfl_xor_sync(0xffffffffu, tm, o);
        }
        if (tid == 0) { redz[0] = tz; redm[0] = tm; }
    }
    __syncthreads();
    const float inv = 1.f / (redm[0] + 1e-13f * redz[0]);

    float a[4];
    a[0] = e0 * m0 * inv; a[1] = e1 * m1 * inv;
    a[2] = e2 * m2 * inv; a[3] = e3 * m3 * inv;

    const size_t o = (size_t)row * L_ + tid * 4;
    bf16 hh[4], ll[4];
#pragma unroll
    for (int i = 0; i < 4; i++) {
        hh[i] = __float2bfloat16(a[i]);
        ll[i] = __float2bfloat16(a[i] - __bfloat162float(hh[i]));
    }
    *(uint2*)(g_ah + o) = *(uint2*)hh;
    *(uint2*)(g_al + o) = *(uint2*)ll;
}

// ---------------------------------------------------------------------------
extern "C" void kernel_launch(void* const* d_in, const int* in_sizes, int n_in,
                              void* d_out, int out_size)
{
    const float* x = (const float*)d_in[0];
    const int* xmask = (const int*)d_in[1];
    float* out = (float*)d_out;

    cudaFuncSetAttribute(gemm_kernel<true>,
                         cudaFuncAttributeMaxDynamicSharedMemorySize, SMEM_GEMM);
    cudaFuncSetAttribute(gemm_kernel<false>,
                         cudaFuncAttributeMaxDynamicSharedMemorySize, SMEM_GEMM);

    conv_kernel<<<dim3(32, 32, B_), dim3(32, 8)>>>(x);

    gemm_kernel<true><<<dim3(8, 4, B_), 512, SMEM_GEMM>>>(xmask, nullptr);

    softmax_kernel<<<B_ * L_, 256>>>(xmask);

    gemm_kernel<false><<<dim3(8, 4, B_), 512, SMEM_GEMM>>>(xmask, out);
}

// round 10
// speedup vs baseline: 1.4309x; 1.2094x over previous
#include <cuda_runtime.h>
#include <cuda_bf16.h>
#include <cstdint>

#define B_ 32
#define L_ 1024
#define D_ 1024
typedef __nv_bfloat16 bf16;

// ---------------------------------------------------------------------------
// Scratch (device globals; no allocation in kernel_launch)
// ---------------------------------------------------------------------------
__device__ bf16  g_xh [(size_t)B_ * L_ * D_];   // x hi split, [b, l, d]
__device__ bf16  g_xl [(size_t)B_ * L_ * D_];   // x lo split
__device__ bf16  g_xth[(size_t)B_ * L_ * D_];   // x^T hi, [b, d, l]
__device__ bf16  g_xtl[(size_t)B_ * L_ * D_];   // x^T lo
__device__ float g_scores[(size_t)B_ * L_ * L_];
__device__ bf16  g_ah [(size_t)B_ * L_ * L_];   // alpha hi
__device__ bf16  g_al [(size_t)B_ * L_ * L_];   // alpha lo

// ---------------------------------------------------------------------------
// PTX helpers (baseline ISA only — harness targets plain sm_103, no tcgen05)
// ---------------------------------------------------------------------------
__device__ __forceinline__ uint32_t smem_u32(const void* p) {
    uint32_t a;
    asm("{ .reg .u64 t; cvta.to.shared.u64 t, %1; cvt.u32.u64 %0, t; }" : "=r"(a) : "l"(p));
    return a;
}
#define CP_COMMIT() asm volatile("cp.async.commit_group;" ::: "memory")
#define CP_WAIT1()  asm volatile("cp.async.wait_group 1;" ::: "memory")
#define CP_WAIT0()  asm volatile("cp.async.wait_group 0;" ::: "memory")

__device__ __forceinline__ void cp16(uint32_t dst, const void* src) {
    asm volatile("cp.async.cg.shared.global [%0], [%1], 16;" :: "r"(dst), "l"(src));
}
__device__ __forceinline__ void ldsm4(uint32_t* r, uint32_t addr) {
    asm volatile("ldmatrix.sync.aligned.m8n8.x4.shared.b16 {%0,%1,%2,%3}, [%4];"
                 : "=r"(r[0]), "=r"(r[1]), "=r"(r[2]), "=r"(r[3]) : "r"(addr));
}
__device__ __forceinline__ void mma16816(float* c, const uint32_t* a, const uint32_t* b) {
    asm volatile(
        "mma.sync.aligned.m16n8k16.row.col.f32.bf16.bf16.f32 "
        "{%0,%1,%2,%3}, {%4,%5,%6,%7}, {%8,%9}, {%0,%1,%2,%3};"
        : "+f"(c[0]), "+f"(c[1]), "+f"(c[2]), "+f"(c[3])
        : "r"(a[0]), "r"(a[1]), "r"(a[2]), "r"(a[3]), "r"(b[0]), "r"(b[1]));
}

// ---------------------------------------------------------------------------
// Kernel 0: split x into bf16 hi/lo, plus transposed copies.
// ---------------------------------------------------------------------------
__global__ __launch_bounds__(256) void conv_kernel(const float* __restrict__ x)
{
    __shared__ bf16 sh[32][33];
    __shared__ bf16 sl[32][33];
    const int b = blockIdx.z;
    const int d0 = blockIdx.x * 32, l0 = blockIdx.y * 32;
    const int tx = threadIdx.x, ty = threadIdx.y;
    const float* X = x + (size_t)b * L_ * D_;
    const size_t bo = (size_t)b * L_ * D_;

#pragma unroll
    for (int i = 0; i < 4; i++) {
        int row = ty + i * 8;
        float v = X[(size_t)(l0 + row) * D_ + d0 + tx];
        bf16 h = __float2bfloat16(v);
        bf16 l = __float2bfloat16(v - __bfloat162float(h));
        size_t o = bo + (size_t)(l0 + row) * D_ + d0 + tx;
        g_xh[o] = h; g_xl[o] = l;
        sh[row][tx] = h; sl[row][tx] = l;
    }
    __syncthreads();
#pragma unroll
    for (int i = 0; i < 4; i++) {
        int row = ty + i * 8;
        size_t o = bo + (size_t)(d0 + row) * L_ + l0 + tx;
        g_xth[o] = sh[tx][row];
        g_xtl[o] = sl[tx][row];
    }
}

// ===========================================================================
// SCORES kernel (symmetric): 128x128 CTA tile, 8 warps, KC=32 2-stage ring,
// 2 CTAs/SM. Grid covers only blocks (i,j) with i>=j (36 per batch).
// The raw S = X.X^T tile is bitwise symmetric under the split scheme, so
// for i>j we stage the tile in smem and write BOTH S_ij and S_ij^T, applying
// diag/mask zeroing per destination element.
// ===========================================================================
#define KC 32
#define TROW 40                         // elements per smem row (80 bytes)
#define TILE_BYTES (128 * TROW * 2)     // 10240
#define STAGE_BYTES (4 * TILE_BYTES)    // 40960: Ah, Al, Bh, Bl
#define SMEM_SC (2 * STAGE_BYTES)       // 81920 >= 128*129*4 transpose stage

__device__ __forceinline__ void fill_tile128(uint32_t dst, const bf16* __restrict__ src,
                                             int rowBase, int k0, int tid)
{
#pragma unroll
    for (int i = 0; i < 2; i++) {
        int idx = i * 256 + tid;          // 0..511
        int row = idx >> 2, seg = idx & 3;
        cp16(dst + row * 80 + seg * 16,
             src + (size_t)(rowBase + row) * 1024 + k0 + seg * 8);
    }
}

__global__ __launch_bounds__(256, 2) void scores_kernel(const int* __restrict__ xmask)
{
    extern __shared__ char smem[];
    const uint32_t sb = smem_u32(smem);
    float* ss = (float*)smem;                       // transpose stage, stride 129
    const int tid = threadIdx.x;
    const int wid = tid >> 5, lane = tid & 31;
    const int wr = wid >> 2, wc = wid & 3;          // 2x4 warp grid
    const int b = blockIdx.z;

    // decode triangular block index: t -> (bi >= bj)
    const int t = blockIdx.x;
    int bi = 0, acc0 = 0;
    while (acc0 + bi + 1 <= t) { bi++; acc0 += bi; }
    const int bj = t - acc0;
    const int rowBase = bi * 128;
    const int colBase = bj * 128;

    const size_t bo = (size_t)b * 1024 * 1024;
    const bf16* Ah = g_xh + bo;
    const bf16* Al = g_xl + bo;
    float* O = g_scores + bo;
    const int* mrow = xmask + b * L_;

    float acc[4][4][4];
#pragma unroll
    for (int i = 0; i < 4; i++)
#pragma unroll
        for (int j = 0; j < 4; j++)
#pragma unroll
            for (int k = 0; k < 4; k++) acc[i][j][k] = 0.f;

    const uint32_t aRowOff = (uint32_t)(wr * 64 + (lane & 15)) * 80;
    const uint32_t aColSel = (uint32_t)(lane >> 4) * 8;
    const uint32_t bRowBase = (uint32_t)(wc * 32 + ((lane >> 4) << 3) + (lane & 7));
    const uint32_t bColSel = (uint32_t)((lane >> 3) & 1) * 8;

#pragma unroll
    for (int s = 0; s < 2; s++) {
        uint32_t st = sb + s * STAGE_BYTES;
        fill_tile128(st + 0 * TILE_BYTES, Ah, rowBase, s * KC, tid);
        fill_tile128(st + 1 * TILE_BYTES, Al, rowBase, s * KC, tid);
        fill_tile128(st + 2 * TILE_BYTES, Ah, colBase, s * KC, tid);
        fill_tile128(st + 3 * TILE_BYTES, Al, colBase, s * KC, tid);
        CP_COMMIT();
    }

    for (int c = 0; c < 32; c++) {
        if (c >= 30) CP_WAIT0(); else CP_WAIT1();
        __syncthreads();
        const uint32_t st = sb + (c & 1) * STAGE_BYTES;

#pragma unroll
        for (int kk = 0; kk < KC; kk += 16) {
            uint32_t bh[2][4], bl[2][4];
#pragma unroll
            for (int n2 = 0; n2 < 2; n2++) {
                uint32_t off = (bRowBase + (uint32_t)n2 * 16) * 80 + (kk + bColSel) * 2;
                ldsm4(bh[n2], st + 2 * TILE_BYTES + off);
                ldsm4(bl[n2], st + 3 * TILE_BYTES + off);
            }
#pragma unroll
            for (int mf = 0; mf < 4; mf++) {
                uint32_t ah[4], al[4];
                uint32_t off = aRowOff + (uint32_t)mf * (16 * 80) + (kk + aColSel) * 2;
                ldsm4(ah, st + 0 * TILE_BYTES + off);
                ldsm4(al, st + 1 * TILE_BYTES + off);
#pragma unroll
                for (int nf = 0; nf < 4; nf++) {
                    const uint32_t* bhp = &bh[nf >> 1][(nf & 1) * 2];
                    const uint32_t* blp = &bl[nf >> 1][(nf & 1) * 2];
                    mma16816(acc[mf][nf], ah, bhp);
                    mma16816(acc[mf][nf], al, bhp);
                    mma16816(acc[mf][nf], ah, blp);
                }
            }
        }
        __syncthreads();
        if (c + 2 < 32) {
            const int k0 = (c + 2) * KC;
            fill_tile128(st + 0 * TILE_BYTES, Ah, rowBase, k0, tid);
            fill_tile128(st + 1 * TILE_BYTES, Al, rowBase, k0, tid);
            fill_tile128(st + 2 * TILE_BYTES, Ah, colBase, k0, tid);
            fill_tile128(st + 3 * TILE_BYTES, Al, colBase, k0, tid);
            CP_COMMIT();
        }
    }

    // ---- direct write of S_ij with its masks (from registers) ----
    const int rb0 = wr * 64 + (lane >> 2);
    const int cb0 = wc * 32 + (lane & 3) * 2;
#pragma unroll
    for (int mf = 0; mf < 4; mf++) {
        const int rl = rb0 + mf * 16;
#pragma unroll
        for (int nf = 0; nf < 4; nf++) {
            const int cl = cb0 + nf * 8;
            const int r = rowBase + rl, r8 = r + 8;
            const int cc = colBase + cl;
            float v0 = acc[mf][nf][0], v1 = acc[mf][nf][1];
            float v2 = acc[mf][nf][2], v3 = acc[mf][nf][3];
            const int m0 = mrow[cc], m1 = mrow[cc + 1];
            float w0 = (r == cc || m0 == 0) ? 0.f : v0;
            float w1 = (r == cc + 1 || m1 == 0) ? 0.f : v1;
            float w2 = (r8 == cc || m0 == 0) ? 0.f : v2;
            float w3 = (r8 == cc + 1 || m1 == 0) ? 0.f : v3;
            *(float2*)(O + (size_t)r * 1024 + cc) = make_float2(w0, w1);
            *(float2*)(O + (size_t)r8 * 1024 + cc) = make_float2(w2, w3);
        }
    }

    if (bi == bj) return;

    // ---- stage raw tile into smem (stride 129), then write S_ij^T ----
    __syncthreads();       // all stage-buffer reads done; safe to overwrite
#pragma unroll
    for (int mf = 0; mf < 4; mf++) {
        const int rl = rb0 + mf * 16;
#pragma unroll
        for (int nf = 0; nf < 4; nf++) {
            const int cl = cb0 + nf * 8;
            // scalar stores: stride 129 is odd, float2 would be misaligned
            ss[rl * 129 + cl]       = acc[mf][nf][0];
            ss[rl * 129 + cl + 1]   = acc[mf][nf][1];
            ss[(rl + 8) * 129 + cl]     = acc[mf][nf][2];
            ss[(rl + 8) * 129 + cl + 1] = acc[mf][nf][3];
        }
    }
    __syncthreads();

    // transposed tile: global row = colBase+cl, cols rowBase..+127, val = ss[rl][cl]
    // mask for this tile's columns: mrow[rowBase + rl]; diag when equal.
    {
        const int4 mk = *(const int4*)(mrow + rowBase + lane * 4);
        const float4 mf4 = make_float4(mk.x ? 1.f : 0.f, mk.y ? 1.f : 0.f,
                                       mk.z ? 1.f : 0.f, mk.w ? 1.f : 0.f);
#pragma unroll
        for (int q = 0; q < 16; q++) {
            const int cl = wid * 16 + q;               // 0..127
            const int grow = colBase + cl;
            const int rl0 = lane * 4;
            float4 v;
            v.x = ss[(rl0 + 0) * 129 + cl] * mf4.x;
            v.y = ss[(rl0 + 1) * 129 + cl] * mf4.y;
            v.z = ss[(rl0 + 2) * 129 + cl] * mf4.z;
            v.w = ss[(rl0 + 3) * 129 + cl] * mf4.w;
            const int d = grow - (rowBase + rl0);      // diag if d in [0,4)
            if (d == 0) v.x = 0.f;
            else if (d == 1) v.y = 0.f;
            else if (d == 2) v.z = 0.f;
            else if (d == 3) v.w = 0.f;
            *(float4*)(O + (size_t)grow * 1024 + rowBase + rl0) = v;
        }
    }
}

// ===========================================================================
// OUT kernel: 256x128 CTA tile, 512 threads, 3-stage ring (unchanged R8).
// ===========================================================================
#define NSTAGE 3
#define NCHUNK (1024 / KC)              // 32
#define ATILE_B (256 * TROW * 2)        // 20480
#define BTILE_B (128 * TROW * 2)        // 10240
#define AH_OFF 0
#define AL_OFF ATILE_B
#define BH_OFF (2 * ATILE_B)
#define BL_OFF (2 * ATILE_B + BTILE_B)
#define OSTAGE_BYTES (2 * ATILE_B + 2 * BTILE_B)   // 61440
#define SMEM_OUT (NSTAGE * OSTAGE_BYTES)           // 184320

__device__ __forceinline__ void fill_stage_out(uint32_t st,
                                               const bf16* __restrict__ Ah,
                                               const bf16* __restrict__ Al,
                                               const bf16* __restrict__ Bh,
                                               const bf16* __restrict__ Bl,
                                               int rowBase, int colBase, int k0, int tid)
{
#pragma unroll
    for (int i = 0; i < 2; i++) {
        int idx = i * 512 + tid;
        int row = idx >> 2, seg = idx & 3;
        uint32_t d = st + row * 80 + seg * 16;
        size_t so = (size_t)(rowBase + row) * 1024 + k0 + seg * 8;
        cp16(d + AH_OFF, Ah + so);
        cp16(d + AL_OFF, Al + so);
    }
    {
        int row = tid >> 2, seg = tid & 3;
        uint32_t d = st + row * 80 + seg * 16;
        size_t so = (size_t)(colBase + row) * 1024 + k0 + seg * 8;
        cp16(d + BH_OFF, Bh + so);
        cp16(d + BL_OFF, Bl + so);
    }
}

__global__ __launch_bounds__(512, 1) void out_kernel(float* __restrict__ gout)
{
    extern __shared__ char smem[];
    const uint32_t sb = smem_u32(smem);
    const int tid = threadIdx.x;
    const int wid = tid >> 5, lane = tid & 31;
    const int wr = wid >> 2, wc = wid & 3;          // 4x4 warp grid
    const int b = blockIdx.z;
    const int rowBase = blockIdx.y * 256;
    const int colBase = blockIdx.x * 128;

    const size_t bo = (size_t)b * 1024 * 1024;
    const bf16* Ah = g_ah + bo;
    const bf16* Al = g_al + bo;
    const bf16* Bh = g_xth + bo;
    const bf16* Bl = g_xtl + bo;
    float* O = gout + bo;

    float acc[4][4][4];
#pragma unroll
    for (int i = 0; i < 4; i++)
#pragma unroll
        for (int j = 0; j < 4; j++)
#pragma unroll
            for (int k = 0; k < 4; k++) acc[i][j][k] = 0.f;

    const uint32_t aRowOff = (uint32_t)(wr * 64 + (lane & 15)) * 80;
    const uint32_t aColSel = (uint32_t)(lane >> 4) * 8;
    const uint32_t bRowBase = (uint32_t)(wc * 32 + ((lane >> 4) << 3) + (lane & 7));
    const uint32_t bColSel = (uint32_t)((lane >> 3) & 1) * 8;

#pragma unroll
    for (int s = 0; s < NSTAGE - 1; s++) {
        fill_stage_out(sb + s * OSTAGE_BYTES, Ah, Al, Bh, Bl, rowBase, colBase, s * KC, tid);
        CP_COMMIT();
    }

    int s_cur = 0, s_nxt = 2;
    for (int c = 0; c < NCHUNK; c++) {
        if (c >= NCHUNK - 1) CP_WAIT0(); else CP_WAIT1();
        __syncthreads();
        const uint32_t st = sb + s_cur * OSTAGE_BYTES;

        if (c + NSTAGE - 1 < NCHUNK) {
            fill_stage_out(sb + s_nxt * OSTAGE_BYTES, Ah, Al, Bh, Bl,
                           rowBase, colBase, (c + NSTAGE - 1) * KC, tid);
            CP_COMMIT();
        }

#pragma unroll
        for (int kk = 0; kk < KC; kk += 16) {
            uint32_t bh[2][4], bl[2][4];
#pragma unroll
            for (int n2 = 0; n2 < 2; n2++) {
                uint32_t off = (bRowBase + (uint32_t)n2 * 16) * 80 + (kk + bColSel) * 2;
                ldsm4(bh[n2], st + BH_OFF + off);
                ldsm4(bl[n2], st + BL_OFF + off);
            }
#pragma unroll
            for (int mf = 0; mf < 4; mf++) {
                uint32_t ah[4], al[4];
                uint32_t off = aRowOff + (uint32_t)mf * (16 * 80) + (kk + aColSel) * 2;
                ldsm4(ah, st + AH_OFF + off);
                ldsm4(al, st + AL_OFF + off);
#pragma unroll
                for (int nf = 0; nf < 4; nf++) {
                    const uint32_t* bhp = &bh[nf >> 1][(nf & 1) * 2];
                    const uint32_t* blp = &bl[nf >> 1][(nf & 1) * 2];
                    mma16816(acc[mf][nf], ah, bhp);
                    mma16816(acc[mf][nf], al, bhp);
                    mma16816(acc[mf][nf], ah, blp);
                }
            }
        }
        s_cur++; if (s_cur == NSTAGE) s_cur = 0;
        s_nxt++; if (s_nxt == NSTAGE) s_nxt = 0;
    }

    const int rb = rowBase + wr * 64 + (lane >> 2);
    const int cb = colBase + wc * 32 + (lane & 3) * 2;
#pragma unroll
    for (int mf = 0; mf < 4; mf++) {
        const int r = rb + mf * 16;
#pragma unroll
        for (int nf = 0; nf < 4; nf++) {
            const int cc = cb + nf * 8;
            *(float2*)(O + (size_t)r * 1024 + cc) = make_float2(acc[mf][nf][0], acc[mf][nf][1]);
            *(float2*)(O + (size_t)(r + 8) * 1024 + cc) = make_float2(acc[mf][nf][2], acc[mf][nf][3]);
        }
    }
}

// ---------------------------------------------------------------------------
// Softmax-renormalize: reads g_scores, writes alpha as bf16 hi/lo splits.
// ---------------------------------------------------------------------------
__global__ __launch_bounds__(256) void softmax_kernel(const int* __restrict__ xmask)
{
    const int row = blockIdx.x;
    const int b = row >> 10;
    const float* srow = g_scores + (size_t)row * L_;
    const int* mrow = xmask + b * L_;
    const int tid = threadIdx.x;

    float4 v = *(const float4*)(srow + tid * 4);
    int4 mk = *(const int4*)(mrow + tid * 4);

    __shared__ float red[8];
    float mx = fmaxf(fmaxf(v.x, v.y), fmaxf(v.z, v.w));
#pragma unroll
    for (int o = 16; o > 0; o >>= 1) mx = fmaxf(mx, __shfl_xor_sync(0xffffffffu, mx, o));
    if ((tid & 31) == 0) red[tid >> 5] = mx;
    __syncthreads();
    if (tid < 32) {
        float t = (tid < 8) ? red[tid] : -3.4e38f;
#pragma unroll
        for (int o = 4; o > 0; o >>= 1) t = fmaxf(t, __shfl_xor_sync(0xffffffffu, t, o));
        if (tid == 0) red[0] = t;
    }
    __syncthreads();
    mx = red[0];
    __syncthreads();

    float e0 = __expf(v.x - mx), e1 = __expf(v.y - mx);
    float e2 = __expf(v.z - mx), e3 = __expf(v.w - mx);
    float m0 = (mk.x != 0) ? 1.f : 0.f, m1 = (mk.y != 0) ? 1.f : 0.f;
    float m2 = (mk.z != 0) ? 1.f : 0.f, m3 = (mk.w != 0) ? 1.f : 0.f;
    float zf = e0 + e1 + e2 + e3;
    float sm = e0 * m0 + e1 * m1 + e2 * m2 + e3 * m3;

    float2 s2 = make_float2(zf, sm);
#pragma unroll
    for (int o = 16; o > 0; o >>= 1) {
        s2.x += __shfl_xor_sync(0xffffffffu, s2.x, o);
        s2.y += __shfl_xor_sync(0xffffffffu, s2.y, o);
    }
    __shared__ float redz[8], redm[8];
    if ((tid & 31) == 0) { redz[tid >> 5] = s2.x; redm[tid >> 5] = s2.y; }
    __syncthreads();
    if (tid < 32) {
        float tz = (tid < 8) ? redz[tid] : 0.f;
        float tm = (tid < 8) ? redm[tid] : 0.f;
#pragma unroll
        for (int o = 4; o > 0; o >>= 1) {
            tz += __shfl_xor_sync(0xffffffffu, tz, o);
            tm += __shfl_xor_sync(0xffffffffu, tm, o);
        }
        if (tid == 0) { redz[0] = tz; redm[0] = tm; }
    }
    __syncthreads();
    const float inv = 1.f / (redm[0] + 1e-13f * redz[0]);

    float a[4];
    a[0] = e0 * m0 * inv; a[1] = e1 * m1 * inv;
    a[2] = e2 * m2 * inv; a[3] = e3 * m3 * inv;

    const size_t o = (size_t)row * L_ + tid * 4;
    bf16 hh[4], ll[4];
#pragma unroll
    for (int i = 0; i < 4; i++) {
        hh[i] = __float2bfloat16(a[i]);
        ll[i] = __float2bfloat16(a[i] - __bfloat162float(hh[i]));
    }
    *(uint2*)(g_ah + o) = *(uint2*)hh;
    *(uint2*)(g_al + o) = *(uint2*)ll;
}

// ---------------------------------------------------------------------------
extern "C" void kernel_launch(void* const* d_in, const int* in_sizes, int n_in,
                              void* d_out, int out_size)
{
    const float* x = (const float*)d_in[0];
    const int* xmask = (const int*)d_in[1];
    float* out = (float*)d_out;

    cudaFuncSetAttribute(scores_kernel,
                         cudaFuncAttributeMaxDynamicSharedMemorySize, SMEM_SC);
    cudaFuncSetAttribute(out_kernel,
                         cudaFuncAttributeMaxDynamicSharedMemorySize, SMEM_OUT);

    conv_kernel<<<dim3(32, 32, B_), dim3(32, 8)>>>(x);

    scores_kernel<<<dim3(36, 1, B_), 256, SMEM_SC>>>(xmask);

    softmax_kernel<<<B_ * L_, 256>>>(xmask);

    out_kernel<<<dim3(8, 4, B_), 512, SMEM_OUT>>>(out);
}

// round 11
// speedup vs baseline: 1.9174x; 1.3400x over previous
#include <cuda_runtime.h>
#include <cuda_bf16.h>
#include <cstdint>

#define B_ 32
#define L_ 1024
#define D_ 1024
typedef __nv_bfloat16 bf16;

// ---------------------------------------------------------------------------
// Scratch (device globals; no allocation in kernel_launch)
// ---------------------------------------------------------------------------
__device__ bf16  g_xh  [(size_t)B_ * L_ * D_];  // x hi split, [b, l, d]
__device__ bf16  g_xl  [(size_t)B_ * L_ * D_];  // x lo split
__device__ bf16  g_xtch[(size_t)B_ * L_ * D_];  // compact x^T hi, [b, d, j]
__device__ bf16  g_xtcl[(size_t)B_ * L_ * D_];  // compact x^T lo
__device__ float g_scores[(size_t)B_ * L_ * L_]; // compact cols [b, r, j<cnt]
__device__ bf16  g_ah  [(size_t)B_ * L_ * L_];  // compact alpha hi
__device__ bf16  g_al  [(size_t)B_ * L_ * L_];  // compact alpha lo
__device__ int   g_idx [B_ * L_];               // valid-column indices (padded w/ 0)
__device__ int   g_pos [B_ * L_];               // exclusive prefix of mask
__device__ int   g_cnt [B_];

// ---------------------------------------------------------------------------
// PTX helpers (baseline ISA only — harness targets plain sm_103, no tcgen05)
// ---------------------------------------------------------------------------
__device__ __forceinline__ uint32_t smem_u32(const void* p) {
    uint32_t a;
    asm("{ .reg .u64 t; cvta.to.shared.u64 t, %1; cvt.u32.u64 %0, t; }" : "=r"(a) : "l"(p));
    return a;
}
#define CP_COMMIT() asm volatile("cp.async.commit_group;" ::: "memory")
#define CP_WAIT1()  asm volatile("cp.async.wait_group 1;" ::: "memory")
#define CP_WAIT0()  asm volatile("cp.async.wait_group 0;" ::: "memory")

__device__ __forceinline__ void cp16(uint32_t dst, const void* src) {
    asm volatile("cp.async.cg.shared.global [%0], [%1], 16;" :: "r"(dst), "l"(src));
}
__device__ __forceinline__ void ldsm4(uint32_t* r, uint32_t addr) {
    asm volatile("ldmatrix.sync.aligned.m8n8.x4.shared.b16 {%0,%1,%2,%3}, [%4];"
                 : "=r"(r[0]), "=r"(r[1]), "=r"(r[2]), "=r"(r[3]) : "r"(addr));
}
__device__ __forceinline__ void mma16816(float* c, const uint32_t* a, const uint32_t* b) {
    asm volatile(
        "mma.sync.aligned.m16n8k16.row.col.f32.bf16.bf16.f32 "
        "{%0,%1,%2,%3}, {%4,%5,%6,%7}, {%8,%9}, {%0,%1,%2,%3};"
        : "+f"(c[0]), "+f"(c[1]), "+f"(c[2]), "+f"(c[3])
        : "r"(a[0]), "r"(a[1]), "r"(a[2]), "r"(a[3]), "r"(b[0]), "r"(b[1]));
}

// ---------------------------------------------------------------------------
// mask_scan: per batch, exclusive prefix of mask -> g_pos, g_idx, g_cnt.
// ---------------------------------------------------------------------------
__global__ __launch_bounds__(256) void mask_scan(const int* __restrict__ xmask)
{
    const int b = blockIdx.x;
    const int tid = threadIdx.x;
    const int lane = tid & 31, wid = tid >> 5;
    const int4 m = *(const int4*)(xmask + b * L_ + tid * 4);
    const int c0 = (m.x != 0), c1 = (m.y != 0), c2 = (m.z != 0), c3 = (m.w != 0);
    const int tot = c0 + c1 + c2 + c3;

    int incl = tot;
#pragma unroll
    for (int o = 1; o < 32; o <<= 1) {
        int v = __shfl_up_sync(0xffffffffu, incl, o);
        if (lane >= o) incl += v;
    }
    __shared__ int ws[8];
    if (lane == 31) ws[wid] = incl;
    __syncthreads();
    if (tid < 8) {
        int v = ws[tid];
#pragma unroll
        for (int o = 1; o < 8; o <<= 1) {
            int u = __shfl_up_sync(0xffu, v, o);
            if (tid >= o) v += u;
        }
        ws[tid] = v;
    }
    __syncthreads();
    int base = (wid > 0 ? ws[wid - 1] : 0) + (incl - tot);
    const int cnt = ws[7];

    const int l = tid * 4;
    int p = base;
    g_pos[b * L_ + l + 0] = p; if (c0) { g_idx[b * L_ + p] = l + 0; p++; }
    g_pos[b * L_ + l + 1] = p; if (c1) { g_idx[b * L_ + p] = l + 1; p++; }
    g_pos[b * L_ + l + 2] = p; if (c2) { g_idx[b * L_ + p] = l + 2; p++; }
    g_pos[b * L_ + l + 3] = p; if (c3) { g_idx[b * L_ + p] = l + 3; p++; }

    if (tid == 0) g_cnt[b] = cnt;
    for (int j = cnt + tid; j < L_; j += 256) g_idx[b * L_ + j] = 0;
}

// ---------------------------------------------------------------------------
// conv: split x into bf16 hi/lo, plus COMPACT transposed copies.
// ---------------------------------------------------------------------------
__global__ __launch_bounds__(256) void conv_kernel(const float* __restrict__ x,
                                                   const int* __restrict__ xmask)
{
    __shared__ bf16 sh[32][33];
    __shared__ bf16 sl[32][33];
    const int b = blockIdx.z;
    const int d0 = blockIdx.x * 32, l0 = blockIdx.y * 32;
    const int tx = threadIdx.x, ty = threadIdx.y;
    const float* X = x + (size_t)b * L_ * D_;
    const size_t bo = (size_t)b * L_ * D_;

#pragma unroll
    for (int i = 0; i < 4; i++) {
        int row = ty + i * 8;
        float v = X[(size_t)(l0 + row) * D_ + d0 + tx];
        bf16 h = __float2bfloat16(v);
        bf16 l = __float2bfloat16(v - __bfloat162float(h));
        size_t o = bo + (size_t)(l0 + row) * D_ + d0 + tx;
        g_xh[o] = h; g_xl[o] = l;
        sh[row][tx] = h; sl[row][tx] = l;
    }
    __syncthreads();
    const int l = l0 + tx;
    const int valid = xmask[b * L_ + l];
    const int col = g_pos[b * L_ + l];
    if (valid != 0) {
#pragma unroll
        for (int i = 0; i < 4; i++) {
            int row = ty + i * 8;     // d-offset
            size_t o = bo + (size_t)(d0 + row) * L_ + col;
            g_xtch[o] = sh[tx][row];
            g_xtcl[o] = sl[tx][row];
        }
    }
}

// pad_zero: zero the compact-transpose pad columns [cnt, cntpad32)
__global__ __launch_bounds__(256) void pad_zero()
{
    const int b = blockIdx.x;
    const int cnt = g_cnt[b];
    const int cp = (cnt + 31) & ~31;
    const int w = cp - cnt;
    if (w == 0) return;
    const size_t bo = (size_t)b * L_ * D_;
    for (int t = threadIdx.x; t < w * 1024; t += 256) {
        int j = cnt + t % w;
        int d = t / w;
        g_xtch[bo + (size_t)d * L_ + j] = __float2bfloat16(0.f);
        g_xtcl[bo + (size_t)d * L_ + j] = __float2bfloat16(0.f);
    }
}

// ===========================================================================
// SCORES kernel (compact cols): 128x128 tile, 8 warps, KC=32 2-stage ring,
// 2 CTAs/SM. Columns are the compact valid set (B rows gathered via g_idx).
// Only diag zeroing applies (all compact columns have mask=1).
// ===========================================================================
#define KC 32
#define TROW 40                         // elements per smem row (80 bytes)
#define TILE_BYTES (128 * TROW * 2)     // 10240
#define STAGE_BYTES (4 * TILE_BYTES)    // 40960: Ah, Al, Bh, Bl
#define SMEM_SC (2 * STAGE_BYTES)       // 81920

__device__ __forceinline__ void fill_tile128(uint32_t dst, const bf16* __restrict__ src,
                                             int rowBase, int k0, int tid)
{
#pragma unroll
    for (int i = 0; i < 2; i++) {
        int idx = i * 256 + tid;
        int row = idx >> 2, seg = idx & 3;
        cp16(dst + row * 80 + seg * 16,
             src + (size_t)(rowBase + row) * 1024 + k0 + seg * 8);
    }
}

__device__ __forceinline__ void fill_tile128_gather(uint32_t dst, const bf16* __restrict__ src,
                                                    const int* __restrict__ idxp,
                                                    int colBase, int k0, int tid)
{
#pragma unroll
    for (int i = 0; i < 2; i++) {
        int idx = i * 256 + tid;
        int row = idx >> 2, seg = idx & 3;
        int gr = idxp[colBase + row];
        cp16(dst + row * 80 + seg * 16,
             src + (size_t)gr * 1024 + k0 + seg * 8);
    }
}

__global__ __launch_bounds__(256, 2) void scores_kernel()
{
    extern __shared__ char smem[];
    const uint32_t sb = smem_u32(smem);
    const int tid = threadIdx.x;
    const int wid = tid >> 5, lane = tid & 31;
    const int wr = wid >> 2, wc = wid & 3;          // 2x4 warp grid
    const int b = blockIdx.z;
    const int cnt = g_cnt[b];
    const int colBase = blockIdx.x * 128;           // compact col tile
    if (colBase >= cnt) return;
    const int rowBase = blockIdx.y * 128;

    const size_t bo = (size_t)b * 1024 * 1024;
    const bf16* Ah = g_xh + bo;
    const bf16* Al = g_xl + bo;
    const int* idxp = g_idx + b * L_;
    float* O = g_scores + bo;

    float acc[4][4][4];
#pragma unroll
    for (int i = 0; i < 4; i++)
#pragma unroll
        for (int j = 0; j < 4; j++)
#pragma unroll
            for (int k = 0; k < 4; k++) acc[i][j][k] = 0.f;

    const uint32_t aRowOff = (uint32_t)(wr * 64 + (lane & 15)) * 80;
    const uint32_t aColSel = (uint32_t)(lane >> 4) * 8;
    const uint32_t bRowBase = (uint32_t)(wc * 32 + ((lane >> 4) << 3) + (lane & 7));
    const uint32_t bColSel = (uint32_t)((lane >> 3) & 1) * 8;

#pragma unroll
    for (int s = 0; s < 2; s++) {
        uint32_t st = sb + s * STAGE_BYTES;
        fill_tile128(st + 0 * TILE_BYTES, Ah, rowBase, s * KC, tid);
        fill_tile128(st + 1 * TILE_BYTES, Al, rowBase, s * KC, tid);
        fill_tile128_gather(st + 2 * TILE_BYTES, Ah, idxp, colBase, s * KC, tid);
        fill_tile128_gather(st + 3 * TILE_BYTES, Al, idxp, colBase, s * KC, tid);
        CP_COMMIT();
    }

    for (int c = 0; c < 32; c++) {
        if (c >= 30) CP_WAIT0(); else CP_WAIT1();
        __syncthreads();
        const uint32_t st = sb + (c & 1) * STAGE_BYTES;

#pragma unroll
        for (int kk = 0; kk < KC; kk += 16) {
            uint32_t bh[2][4], bl[2][4];
#pragma unroll
            for (int n2 = 0; n2 < 2; n2++) {
                uint32_t off = (bRowBase + (uint32_t)n2 * 16) * 80 + (kk + bColSel) * 2;
                ldsm4(bh[n2], st + 2 * TILE_BYTES + off);
                ldsm4(bl[n2], st + 3 * TILE_BYTES + off);
            }
#pragma unroll
            for (int mf = 0; mf < 4; mf++) {
                uint32_t ah[4], al[4];
                uint32_t off = aRowOff + (uint32_t)mf * (16 * 80) + (kk + aColSel) * 2;
                ldsm4(ah, st + 0 * TILE_BYTES + off);
                ldsm4(al, st + 1 * TILE_BYTES + off);
#pragma unroll
                for (int nf = 0; nf < 4; nf++) {
                    const uint32_t* bhp = &bh[nf >> 1][(nf & 1) * 2];
                    const uint32_t* blp = &bl[nf >> 1][(nf & 1) * 2];
                    mma16816(acc[mf][nf], ah, bhp);
                    mma16816(acc[mf][nf], al, bhp);
                    mma16816(acc[mf][nf], ah, blp);
                }
            }
        }
        __syncthreads();
        if (c + 2 < 32) {
            const int k0 = (c + 2) * KC;
            fill_tile128(st + 0 * TILE_BYTES, Ah, rowBase, k0, tid);
            fill_tile128(st + 1 * TILE_BYTES, Al, rowBase, k0, tid);
            fill_tile128_gather(st + 2 * TILE_BYTES, Ah, idxp, colBase, k0, tid);
            fill_tile128_gather(st + 3 * TILE_BYTES, Al, idxp, colBase, k0, tid);
            CP_COMMIT();
        }
    }

    // write compact S tile; zero where idx[j] == r (diag)
    const int rb0 = wr * 64 + (lane >> 2);
    const int cb0 = wc * 32 + (lane & 3) * 2;
#pragma unroll
    for (int mf = 0; mf < 4; mf++) {
        const int rl = rb0 + mf * 16;
#pragma unroll
        for (int nf = 0; nf < 4; nf++) {
            const int cl = cb0 + nf * 8;
            const int r = rowBase + rl, r8 = r + 8;
            const int j = colBase + cl;
            const int i0 = idxp[j], i1 = idxp[j + 1];
            float v0 = (i0 == r) ? 0.f : acc[mf][nf][0];
            float v1 = (i1 == r) ? 0.f : acc[mf][nf][1];
            float v2 = (i0 == r8) ? 0.f : acc[mf][nf][2];
            float v3 = (i1 == r8) ? 0.f : acc[mf][nf][3];
            *(float2*)(O + (size_t)r * 1024 + j) = make_float2(v0, v1);
            *(float2*)(O + (size_t)r8 * 1024 + j) = make_float2(v2, v3);
        }
    }
}

// ---------------------------------------------------------------------------
// Softmax on compact columns.
// mx = max(0, compact max); e_j = exp(s_j - mx); sm = sum e_j
// denom = sm + 1e-13 * (sm + (1024 - cnt) * exp(-mx)); alpha_j = e_j / denom
// Writes alpha splits, zero-padded to cntpad32.
// ---------------------------------------------------------------------------
__global__ __launch_bounds__(256) void softmax_kernel()
{
    const int row = blockIdx.x;
    const int b = row >> 10;
    const int cnt = g_cnt[b];
    const int cp = (cnt + 31) & ~31;
    const float* srow = g_scores + (size_t)row * L_;
    const int tid = threadIdx.x;
    const int j4 = tid * 4;

    float s[4];
    int pres[4];
    if (j4 + 4 <= cnt) {
        float4 v = *(const float4*)(srow + j4);
        s[0] = v.x; s[1] = v.y; s[2] = v.z; s[3] = v.w;
        pres[0] = pres[1] = pres[2] = pres[3] = 1;
    } else {
#pragma unroll
        for (int k = 0; k < 4; k++) {
            int j = j4 + k;
            pres[k] = (j < cnt);
            s[k] = pres[k] ? srow[j] : 0.f;
        }
    }

    __shared__ float red[8];
    float mx = fmaxf(fmaxf(fmaxf(s[0], s[1]), fmaxf(s[2], s[3])), 0.f);
#pragma unroll
    for (int o = 16; o > 0; o >>= 1) mx = fmaxf(mx, __shfl_xor_sync(0xffffffffu, mx, o));
    if ((tid & 31) == 0) red[tid >> 5] = mx;
    __syncthreads();
    if (tid < 32) {
        float t = (tid < 8) ? red[tid] : 0.f;
#pragma unroll
        for (int o = 4; o > 0; o >>= 1) t = fmaxf(t, __shfl_xor_sync(0xffffffffu, t, o));
        if (tid == 0) red[0] = t;
    }
    __syncthreads();
    mx = red[0];
    __syncthreads();

    float e[4];
#pragma unroll
    for (int k = 0; k < 4; k++) e[k] = pres[k] ? __expf(s[k] - mx) : 0.f;
    float sm = e[0] + e[1] + e[2] + e[3];
#pragma unroll
    for (int o = 16; o > 0; o >>= 1) sm += __shfl_xor_sync(0xffffffffu, sm, o);
    __shared__ float redm[8];
    if ((tid & 31) == 0) redm[tid >> 5] = sm;
    __syncthreads();
    if (tid < 32) {
        float t = (tid < 8) ? redm[tid] : 0.f;
#pragma unroll
        for (int o = 4; o > 0; o >>= 1) t += __shfl_xor_sync(0xffffffffu, t, o);
        if (tid == 0) redm[0] = t;
    }
    __syncthreads();
    sm = redm[0];

    const float denom = sm + 1e-13f * (sm + (float)(L_ - cnt) * __expf(-mx));
    const float inv = 1.f / denom;

    if (j4 < cp) {
        bf16 hh[4], ll[4];
#pragma unroll
        for (int k = 0; k < 4; k++) {
            float a = e[k] * inv;
            hh[k] = __float2bfloat16(a);
            ll[k] = __float2bfloat16(a - __bfloat162float(hh[k]));
        }
        const size_t o = (size_t)row * L_ + j4;
        *(uint2*)(g_ah + o) = *(uint2*)hh;
        *(uint2*)(g_al + o) = *(uint2*)ll;
    }
}

// ===========================================================================
// OUT kernel: 256x128 CTA tile, 512 threads, 3-stage ring, runtime K=cntpad32.
// A = compact alpha splits; B = compact x^T splits.
// ===========================================================================
#define NSTAGE 3
#define ATILE_B (256 * TROW * 2)        // 20480
#define BTILE_B (128 * TROW * 2)        // 10240
#define AH_OFF 0
#define AL_OFF ATILE_B
#define BH_OFF (2 * ATILE_B)
#define BL_OFF (2 * ATILE_B + BTILE_B)
#define OSTAGE_BYTES (2 * ATILE_B + 2 * BTILE_B)   // 61440
#define SMEM_OUT (NSTAGE * OSTAGE_BYTES)           // 184320

__device__ __forceinline__ void fill_stage_out(uint32_t st,
                                               const bf16* __restrict__ Ah,
                                               const bf16* __restrict__ Al,
                                               const bf16* __restrict__ Bh,
                                               const bf16* __restrict__ Bl,
                                               int rowBase, int colBase, int k0, int tid)
{
#pragma unroll
    for (int i = 0; i < 2; i++) {
        int idx = i * 512 + tid;
        int row = idx >> 2, seg = idx & 3;
        uint32_t d = st + row * 80 + seg * 16;
        size_t so = (size_t)(rowBase + row) * 1024 + k0 + seg * 8;
        cp16(d + AH_OFF, Ah + so);
        cp16(d + AL_OFF, Al + so);
    }
    {
        int row = tid >> 2, seg = tid & 3;
        uint32_t d = st + row * 80 + seg * 16;
        size_t so = (size_t)(colBase + row) * 1024 + k0 + seg * 8;
        cp16(d + BH_OFF, Bh + so);
        cp16(d + BL_OFF, Bl + so);
    }
}

__global__ __launch_bounds__(512, 1) void out_kernel(float* __restrict__ gout)
{
    extern __shared__ char smem[];
    const uint32_t sb = smem_u32(smem);
    const int tid = threadIdx.x;
    const int wid = tid >> 5, lane = tid & 31;
    const int wr = wid >> 2, wc = wid & 3;          // 4x4 warp grid
    const int b = blockIdx.z;
    const int rowBase = blockIdx.y * 256;
    const int colBase = blockIdx.x * 128;
    const int cnt = g_cnt[b];
    const int nch = (cnt + 31) >> 5;

    const size_t bo = (size_t)b * 1024 * 1024;
    const bf16* Ah = g_ah + bo;
    const bf16* Al = g_al + bo;
    const bf16* Bh = g_xtch + bo;
    const bf16* Bl = g_xtcl + bo;
    float* O = gout + bo;

    float acc[4][4][4];
#pragma unroll
    for (int i = 0; i < 4; i++)
#pragma unroll
        for (int j = 0; j < 4; j++)
#pragma unroll
            for (int k = 0; k < 4; k++) acc[i][j][k] = 0.f;

    const uint32_t aRowOff = (uint32_t)(wr * 64 + (lane & 15)) * 80;
    const uint32_t aColSel = (uint32_t)(lane >> 4) * 8;
    const uint32_t bRowBase = (uint32_t)(wc * 32 + ((lane >> 4) << 3) + (lane & 7));
    const uint32_t bColSel = (uint32_t)((lane >> 3) & 1) * 8;

    // prologue: fill 2 stages (addresses always in-bounds; unused stages harmless)
#pragma unroll
    for (int s = 0; s < NSTAGE - 1; s++) {
        fill_stage_out(sb + s * OSTAGE_BYTES, Ah, Al, Bh, Bl, rowBase, colBase, s * KC, tid);
        CP_COMMIT();
    }

    int s_cur = 0, s_nxt = 2;
    for (int c = 0; c < nch; c++) {
        if (c >= nch - 1) CP_WAIT0(); else CP_WAIT1();
        __syncthreads();
        const uint32_t st = sb + s_cur * OSTAGE_BYTES;

        if (c + NSTAGE - 1 < nch) {
            fill_stage_out(sb + s_nxt * OSTAGE_BYTES, Ah, Al, Bh, Bl,
                           rowBase, colBase, (c + NSTAGE - 1) * KC, tid);
            CP_COMMIT();
        }

#pragma unroll
        for (int kk = 0; kk < KC; kk += 16) {
            uint32_t bh[2][4], bl[2][4];
#pragma unroll
            for (int n2 = 0; n2 < 2; n2++) {
                uint32_t off = (bRowBase + (uint32_t)n2 * 16) * 80 + (kk + bColSel) * 2;
                ldsm4(bh[n2], st + BH_OFF + off);
                ldsm4(bl[n2], st + BL_OFF + off);
            }
#pragma unroll
            for (int mf = 0; mf < 4; mf++) {
                uint32_t ah[4], al[4];
                uint32_t off = aRowOff + (uint32_t)mf * (16 * 80) + (kk + aColSel) * 2;
                ldsm4(ah, st + AH_OFF + off);
                ldsm4(al, st + AL_OFF + off);
#pragma unroll
                for (int nf = 0; nf < 4; nf++) {
                    const uint32_t* bhp = &bh[nf >> 1][(nf & 1) * 2];
                    const uint32_t* blp = &bl[nf >> 1][(nf & 1) * 2];
                    mma16816(acc[mf][nf], ah, bhp);
                    mma16816(acc[mf][nf], al, bhp);
                    mma16816(acc[mf][nf], ah, blp);
                }
            }
        }
        s_cur++; if (s_cur == NSTAGE) s_cur = 0;
        s_nxt++; if (s_nxt == NSTAGE) s_nxt = 0;
    }

    const int rb = rowBase + wr * 64 + (lane >> 2);
    const int cb = colBase + wc * 32 + (lane & 3) * 2;
#pragma unroll
    for (int mf = 0; mf < 4; mf++) {
        const int r = rb + mf * 16;
#pragma unroll
        for (int nf = 0; nf < 4; nf++) {
            const int cc = cb + nf * 8;
            *(float2*)(O + (size_t)r * 1024 + cc) = make_float2(acc[mf][nf][0], acc[mf][nf][1]);
            *(float2*)(O + (size_t)(r + 8) * 1024 + cc) = make_float2(acc[mf][nf][2], acc[mf][nf][3]);
        }
    }
}

// ---------------------------------------------------------------------------
extern "C" void kernel_launch(void* const* d_in, const int* in_sizes, int n_in,
                              void* d_out, int out_size)
{
    const float* x = (const float*)d_in[0];
    const int* xmask = (const int*)d_in[1];
    float* out = (float*)d_out;

    cudaFuncSetAttribute(scores_kernel,
                         cudaFuncAttributeMaxDynamicSharedMemorySize, SMEM_SC);
    cudaFuncSetAttribute(out_kernel,
                         cudaFuncAttributeMaxDynamicSharedMemorySize, SMEM_OUT);

    mask_scan<<<B_, 256>>>(xmask);

    conv_kernel<<<dim3(32, 32, B_), dim3(32, 8)>>>(x, xmask);

    pad_zero<<<B_, 256>>>();

    scores_kernel<<<dim3(8, 8, B_), 256, SMEM_SC>>>();

    softmax_kernel<<<B_ * L_, 256>>>();

    out_kernel<<<dim3(8, 4, B_), 512, SMEM_OUT>>>(out);
}